// round 1
// baseline (speedup 1.0000x reference)
#include <cuda_runtime.h>

// Problem constants
#define B_   32
#define N_   4096
#define C_   128     // C_IN
#define O_   128     // C_OUT
#define M_   256

// Scratch (device globals — no allocation allowed)
__device__ float g_xspec[B_ * M_ * C_];    // [b][m][c]  4 MB
__device__ float g_outspec[B_ * M_ * O_];  // [b][m][o]  4 MB
__device__ float g_wt[M_ * C_ * O_];       // [m][c][o] 16 MB

// ---------------------------------------------------------------------------
// K1: x_spec[b,m,c] = sum_n U[n,m] * x[b,n,c]
// Per-batch GEMM: (M x N) * (N x C). Both operands K(n)-major with the
// non-K dim contiguous -> fully coalesced tile loads.
// Block tile 64(m) x 64(c), KT=32, 256 threads, 4x4 register micro-tile.
// grid: (M/64=4, C/64=2, B=32)
// ---------------------------------------------------------------------------
__global__ __launch_bounds__(256) void k1_project(const float* __restrict__ x,
                                                  const float* __restrict__ U) {
    __shared__ float Us[32][64];
    __shared__ float Xs[32][64];
    const int m0 = blockIdx.x * 64;
    const int c0 = blockIdx.y * 64;
    const int b  = blockIdx.z;
    const int tid = threadIdx.x;
    const int ty = tid >> 4;      // 0..15 (m micro-row)
    const int tx = tid & 15;      // 0..15 (c micro-col)

    const float* xb = x + (size_t)b * N_ * C_;

    float acc[4][4];
#pragma unroll
    for (int i = 0; i < 4; i++)
#pragma unroll
        for (int j = 0; j < 4; j++) acc[i][j] = 0.f;

    for (int k0 = 0; k0 < N_; k0 += 32) {
        // Load 32x64 tiles of U and x (512 float4 each, 2 per thread each)
#pragma unroll
        for (int i = 0; i < 2; i++) {
            int t  = tid + i * 256;       // 0..511
            int k  = t >> 4;              // 0..31
            int mv = (t & 15) << 2;       // 0..60
            float4 uv = *(const float4*)(U  + (size_t)(k0 + k) * M_ + m0 + mv);
            *(float4*)(&Us[k][mv]) = uv;
            float4 xv = *(const float4*)(xb + (size_t)(k0 + k) * C_ + c0 + mv);
            *(float4*)(&Xs[k][mv]) = xv;
        }
        __syncthreads();

#pragma unroll
        for (int k = 0; k < 32; k++) {
            float4 a4 = *(float4*)(&Us[k][ty << 2]);
            float4 b4 = *(float4*)(&Xs[k][tx << 2]);
            float av[4] = {a4.x, a4.y, a4.z, a4.w};
            float bv[4] = {b4.x, b4.y, b4.z, b4.w};
#pragma unroll
            for (int i = 0; i < 4; i++)
#pragma unroll
                for (int j = 0; j < 4; j++)
                    acc[i][j] += av[i] * bv[j];
        }
        __syncthreads();
    }

#pragma unroll
    for (int i = 0; i < 4; i++) {
        float4 v = make_float4(acc[i][0], acc[i][1], acc[i][2], acc[i][3]);
        *(float4*)(g_xspec + ((size_t)b * M_ + m0 + (ty << 2) + i) * C_ + c0 + (tx << 2)) = v;
    }
}

// ---------------------------------------------------------------------------
// K2a: transpose W [CO=16384, M=256] row-major  ->  Wt [M, CO] row-major
// (W_real[c,o,m] has m innermost; Wt[m][c][o] makes K2 reads coalesced)
// grid (CO/32=512, M/32=8), block (32,8)
// ---------------------------------------------------------------------------
__global__ __launch_bounds__(256) void k2a_transpose(const float* __restrict__ W) {
    __shared__ float t[32][33];
    const int co0 = blockIdx.x * 32;
    const int m0  = blockIdx.y * 32;
    const int tx = threadIdx.x, ty = threadIdx.y;
#pragma unroll
    for (int i = 0; i < 32; i += 8)
        t[ty + i][tx] = W[(size_t)(co0 + ty + i) * M_ + m0 + tx];
    __syncthreads();
#pragma unroll
    for (int i = 0; i < 32; i += 8)
        g_wt[(size_t)(m0 + ty + i) * (C_ * O_) + co0 + tx] = t[tx][ty + i];
}

// ---------------------------------------------------------------------------
// K2: out_spec[b,m,o] = sum_c x_spec[b,m,c] * Wt[m][c][o]
// One block per mode m. 256 threads: thread = (bh in {0,1}, o in 0..127),
// each thread accumulates 16 b-rows across c.
// ---------------------------------------------------------------------------
__global__ __launch_bounds__(256) void k2_mix() {
    __shared__ float xs[B_][C_];   // 16 KB
    const int m = blockIdx.x;
    const int tid = threadIdx.x;

    for (int i = tid; i < B_ * C_; i += 256) {
        int b = i >> 7, c = i & 127;
        xs[b][c] = g_xspec[((size_t)b * M_ + m) * C_ + c];
    }
    __syncthreads();

    const int o  = tid & 127;
    const int bh = tid >> 7;       // 0 or 1
    const float* w = g_wt + (size_t)m * C_ * O_;

    float acc[16];
#pragma unroll
    for (int i = 0; i < 16; i++) acc[i] = 0.f;

#pragma unroll 4
    for (int c = 0; c < C_; c++) {
        float wv = w[c * O_ + o];
#pragma unroll
        for (int bb = 0; bb < 16; bb++)
            acc[bb] += xs[bb * 2 + bh][c] * wv;
    }

#pragma unroll
    for (int bb = 0; bb < 16; bb++)
        g_outspec[((size_t)(bb * 2 + bh) * M_ + m) * O_ + o] = acc[bb];
}

// ---------------------------------------------------------------------------
// K3: out[b,n,o] = sum_m U[n,m] * out_spec[b,m,o]
// Per-batch GEMM: (N x M) * (M x O). U is row-major [n][m] (k=m contiguous
// per row) -> load coalesced, store transposed into smem with padding.
// Block tile 64(n) x 64(o), KT=32, 256 threads, 4x4 micro-tile.
// grid: (N/64=64, O/64=2, B=32) = 4096 blocks
// ---------------------------------------------------------------------------
__global__ __launch_bounds__(256) void k3_inverse(const float* __restrict__ U,
                                                  float* __restrict__ out) {
    __shared__ float Us[32][65];   // [k][n], padded
    __shared__ float Ss[32][64];   // [k][o]
    const int n0 = blockIdx.x * 64;
    const int o0 = blockIdx.y * 64;
    const int b  = blockIdx.z;
    const int tid = threadIdx.x;
    const int ty = tid >> 4;
    const int tx = tid & 15;

    const float* Sb = g_outspec + (size_t)b * M_ * O_;

    float acc[4][4];
#pragma unroll
    for (int i = 0; i < 4; i++)
#pragma unroll
        for (int j = 0; j < 4; j++) acc[i][j] = 0.f;

    for (int k0 = 0; k0 < M_; k0 += 32) {
        // U tile: 64 n-rows x 32 k — coalesced global read, transposed smem store
#pragma unroll
        for (int i = 0; i < 8; i++) {
            int t = tid + i * 256;    // 0..2047
            int n = t >> 5;           // 0..63
            int k = t & 31;           // 0..31
            Us[k][n] = U[(size_t)(n0 + n) * M_ + k0 + k];
        }
        // S tile: 32 k-rows x 64 o — float4 coalesced
#pragma unroll
        for (int i = 0; i < 2; i++) {
            int t  = tid + i * 256;
            int k  = t >> 4;
            int ov = (t & 15) << 2;
            *(float4*)(&Ss[k][ov]) =
                *(const float4*)(Sb + (size_t)(k0 + k) * O_ + o0 + ov);
        }
        __syncthreads();

#pragma unroll
        for (int k = 0; k < 32; k++) {
            float av[4];
#pragma unroll
            for (int i = 0; i < 4; i++) av[i] = Us[k][(ty << 2) + i];
            float4 b4 = *(float4*)(&Ss[k][tx << 2]);
            float bv[4] = {b4.x, b4.y, b4.z, b4.w};
#pragma unroll
            for (int i = 0; i < 4; i++)
#pragma unroll
                for (int j = 0; j < 4; j++)
                    acc[i][j] += av[i] * bv[j];
        }
        __syncthreads();
    }

#pragma unroll
    for (int i = 0; i < 4; i++) {
        float4 v = make_float4(acc[i][0], acc[i][1], acc[i][2], acc[i][3]);
        *(float4*)(out + ((size_t)b * N_ + n0 + (ty << 2) + i) * O_ + o0 + (tx << 2)) = v;
    }
}

// ---------------------------------------------------------------------------
extern "C" void kernel_launch(void* const* d_in, const int* in_sizes, int n_in,
                              void* d_out, int out_size) {
    const float* x = (const float*)d_in[0];   // [B, N, C_IN]
    const float* U = (const float*)d_in[1];   // [N, M]
    const float* W = (const float*)d_in[2];   // [C_IN, C_OUT, M]
    // d_in[3] = W_imag: mathematically unused (output = Re part only)
    float* out = (float*)d_out;

    // Stage W transpose (independent of K1, ordered on same stream anyway)
    {
        dim3 grid(C_ * O_ / 32, M_ / 32);
        dim3 block(32, 8);
        k2a_transpose<<<grid, block>>>(W);
    }
    // Graph Fourier projection
    {
        dim3 grid(M_ / 64, C_ / 64, B_);
        k1_project<<<grid, 256>>>(x, U);
    }
    // Per-mode spectral channel mixing
    {
        k2_mix<<<M_, 256>>>();
    }
    // Inverse transform
    {
        dim3 grid(N_ / 64, O_ / 64, B_);
        k3_inverse<<<grid, 256>>>(U, out);
    }
}

// round 3
// speedup vs baseline: 3.5009x; 3.5009x over previous
#include <cuda_runtime.h>
#include <cuda_bf16.h>
#include <cstdint>

#define B_   32
#define N_   4096
#define C_   128
#define O_   128
#define M_   256

// ---------------- scratch (device globals; no allocation allowed) ----------
__device__ __align__(16) float g_xspec[B_ * M_ * C_];     // [b][m][c]
__device__ __align__(16) float g_outspec[B_ * M_ * O_];   // [b][m][o]
__device__ __align__(16) float g_wt[M_ * C_ * O_];        // [m][c][o]
__device__ __align__(16) float g_part[2 * B_ * M_ * C_];  // split-K partials (8 MB)

__device__ __align__(128) __nv_bfloat16 g_Uhi[N_ * M_];   // [n][m]  (A for K3)
__device__ __align__(128) __nv_bfloat16 g_Ulo[N_ * M_];
__device__ __align__(128) __nv_bfloat16 g_Uthi[M_ * N_];  // [m][n]  (A for K1)
__device__ __align__(128) __nv_bfloat16 g_Utlo[M_ * N_];
__device__ __align__(128) __nv_bfloat16 g_xthi[(size_t)B_ * C_ * N_]; // [b][c][n] (B for K1)
__device__ __align__(128) __nv_bfloat16 g_xtlo[(size_t)B_ * C_ * N_];
__device__ __align__(128) __nv_bfloat16 g_sthi[B_ * O_ * M_];         // [b][o][m] (B for K3)
__device__ __align__(128) __nv_bfloat16 g_stlo[B_ * O_ * M_];

// ---------------- helpers ---------------------------------------------------
__device__ __forceinline__ uint32_t smem_u32(const void* p) {
    uint32_t a;
    asm("{ .reg .u64 t; cvta.to.shared.u64 t, %1; cvt.u32.u64 %0, t; }" : "=r"(a) : "l"(p));
    return a;
}
__device__ __forceinline__ void cp16(uint32_t dst, const void* src) {
    asm volatile("cp.async.cg.shared.global [%0], [%1], 16;" :: "r"(dst), "l"(src));
}
__device__ __forceinline__ void cp_commit() {
    asm volatile("cp.async.commit_group;" ::: "memory");
}
__device__ __forceinline__ void ldsm4(uint32_t& r0, uint32_t& r1, uint32_t& r2, uint32_t& r3,
                                      uint32_t addr) {
    asm volatile("ldmatrix.sync.aligned.m8n8.x4.shared.b16 {%0,%1,%2,%3}, [%4];"
                 : "=r"(r0), "=r"(r1), "=r"(r2), "=r"(r3) : "r"(addr));
}
__device__ __forceinline__ void mma_bf16(float* d, const uint32_t* a, const uint32_t* b) {
    asm volatile("mma.sync.aligned.m16n8k16.row.col.f32.bf16.bf16.f32 "
                 "{%0,%1,%2,%3}, {%4,%5,%6,%7}, {%8,%9}, {%0,%1,%2,%3};"
                 : "+f"(d[0]), "+f"(d[1]), "+f"(d[2]), "+f"(d[3])
                 : "r"(a[0]), "r"(a[1]), "r"(a[2]), "r"(a[3]), "r"(b[0]), "r"(b[1]));
}
__device__ __forceinline__ void split2(float v, __nv_bfloat16& h, __nv_bfloat16& l) {
    h = __float2bfloat16_rn(v);
    l = __float2bfloat16_rn(v - __bfloat162float(h));
}

// ---------------- prep kernels ---------------------------------------------
__global__ __launch_bounds__(256) void p1_splitU(const float* __restrict__ U) {
    __shared__ float t[32][33];
    const int m0 = blockIdx.x * 32, n0 = blockIdx.y * 32;
    const int tx = threadIdx.x, ty = threadIdx.y;
#pragma unroll
    for (int i = 0; i < 32; i += 8) {
        float v = U[(size_t)(n0 + ty + i) * M_ + m0 + tx];
        t[ty + i][tx] = v;
        __nv_bfloat16 h, l; split2(v, h, l);
        g_Uhi[(size_t)(n0 + ty + i) * M_ + m0 + tx] = h;
        g_Ulo[(size_t)(n0 + ty + i) * M_ + m0 + tx] = l;
    }
    __syncthreads();
#pragma unroll
    for (int i = 0; i < 32; i += 8) {
        float v = t[tx][ty + i];
        __nv_bfloat16 h, l; split2(v, h, l);
        g_Uthi[(size_t)(m0 + ty + i) * N_ + n0 + tx] = h;
        g_Utlo[(size_t)(m0 + ty + i) * N_ + n0 + tx] = l;
    }
}

__global__ __launch_bounds__(256) void p2_splitx(const float* __restrict__ x) {
    __shared__ float t[32][33];
    const int c0 = blockIdx.x * 32, n0 = blockIdx.y * 32, b = blockIdx.z;
    const int tx = threadIdx.x, ty = threadIdx.y;
#pragma unroll
    for (int i = 0; i < 32; i += 8)
        t[ty + i][tx] = x[((size_t)b * N_ + n0 + ty + i) * C_ + c0 + tx];
    __syncthreads();
#pragma unroll
    for (int i = 0; i < 32; i += 8) {
        float v = t[tx][ty + i];
        __nv_bfloat16 h, l; split2(v, h, l);
        g_xthi[((size_t)b * C_ + c0 + ty + i) * N_ + n0 + tx] = h;
        g_xtlo[((size_t)b * C_ + c0 + ty + i) * N_ + n0 + tx] = l;
    }
}

__global__ __launch_bounds__(256) void p3_splitS() {
    __shared__ float t[32][33];
    const int o0 = blockIdx.x * 32, m0 = blockIdx.y * 32, b = blockIdx.z;
    const int tx = threadIdx.x, ty = threadIdx.y;
#pragma unroll
    for (int i = 0; i < 32; i += 8)
        t[ty + i][tx] = g_outspec[((size_t)b * M_ + m0 + ty + i) * O_ + o0 + tx];
    __syncthreads();
#pragma unroll
    for (int i = 0; i < 32; i += 8) {
        float v = t[tx][ty + i];
        __nv_bfloat16 h, l; split2(v, h, l);
        g_sthi[((size_t)b * O_ + o0 + ty + i) * M_ + m0 + tx] = h;
        g_stlo[((size_t)b * O_ + o0 + ty + i) * M_ + m0 + tx] = l;
    }
}

__global__ __launch_bounds__(256) void k2a_transpose(const float* __restrict__ W) {
    __shared__ float t[32][33];
    const int co0 = blockIdx.x * 32, m0 = blockIdx.y * 32;
    const int tx = threadIdx.x, ty = threadIdx.y;
#pragma unroll
    for (int i = 0; i < 32; i += 8)
        t[ty + i][tx] = W[(size_t)(co0 + ty + i) * M_ + m0 + tx];
    __syncthreads();
#pragma unroll
    for (int i = 0; i < 32; i += 8)
        g_wt[(size_t)(m0 + ty + i) * (C_ * O_) + co0 + tx] = t[tx][ty + i];
}

__global__ __launch_bounds__(256) void k2_mix() {
    __shared__ float xs[B_][C_];
    const int m = blockIdx.x;
    const int tid = threadIdx.x;
    for (int i = tid; i < B_ * C_; i += 256) {
        int b = i >> 7, c = i & 127;
        xs[b][c] = g_xspec[((size_t)b * M_ + m) * C_ + c];
    }
    __syncthreads();
    const int o = tid & 127;
    const int bh = tid >> 7;
    const float* w = g_wt + (size_t)m * C_ * O_;
    float acc[16];
#pragma unroll
    for (int i = 0; i < 16; i++) acc[i] = 0.f;
#pragma unroll 4
    for (int c = 0; c < C_; c++) {
        float wv = w[c * O_ + o];
#pragma unroll
        for (int bb = 0; bb < 16; bb++)
            acc[bb] += xs[bb * 2 + bh][c] * wv;
    }
#pragma unroll
    for (int bb = 0; bb < 16; bb++)
        g_outspec[((size_t)(bb * 2 + bh) * M_ + m) * O_ + o] = acc[bb];
}

// reduce split-K partials: g_xspec = part0 + part1 (float4)
__global__ __launch_bounds__(256) void reduce2() {
    const size_t i = (size_t)blockIdx.x * 256 + threadIdx.x;   // float4 index
    const float4 a = ((const float4*)g_part)[i];
    const float4 b = ((const float4*)(g_part + (size_t)B_ * M_ * C_))[i];
    float4 r; r.x = a.x + b.x; r.y = a.y + b.y; r.z = a.z + b.z; r.w = a.w + b.w;
    ((float4*)g_xspec)[i] = r;
}

// ---------------- HMMA bf16-split GEMM (mma.sync path, sm_80 ISA) ----------
// D[128,128] = sum_k A[row,k]*B[col,k], A/B K-major bf16 hi/lo, 3-product split.
// CTA tile 128x128, KC=64 per stage, 2-stage cp.async double buffer.
// smem per stage: 4 mats x [128 rows][64 bf16 =128B] = 64KB; total 128KB.
#define KC        64
#define MATB      16384
#define STAGEB    65536
#define GEMM_SMEM 131072

template <int MODE>   // 0: K1 (split-K=2), 1: K3
__global__ __launch_bounds__(256, 1) void gemm_hmma(float* __restrict__ outp) {
    extern __shared__ char smem[];
    const uint32_t sb = smem_u32(smem);
    const int tid = threadIdx.x, wid = tid >> 5, lane = tid & 31;
    const int rt = blockIdx.x, ks = blockIdx.y, b = blockIdx.z;

    constexpr int LD   = (MODE == 0) ? N_ : M_;       // K-major row stride
    constexpr int KLEN = (MODE == 0) ? (N_ / 2) : M_; // K per CTA
    constexpr int NS   = KLEN / KC;

    const __nv_bfloat16 *pAh, *pAl, *pBh, *pBl;
    float* po;
    if (MODE == 0) {
        const size_t aoff = (size_t)rt * 128 * N_ + (size_t)ks * KLEN;
        const size_t boff = (size_t)b * 128 * N_ + (size_t)ks * KLEN;
        pAh = g_Uthi + aoff; pAl = g_Utlo + aoff;
        pBh = g_xthi + boff; pBl = g_xtlo + boff;
        po = g_part + (size_t)ks * (B_ * M_ * C_) + (size_t)(b * 2 + rt) * (128 * 128);
    } else {
        const size_t aoff = (size_t)rt * 128 * M_;
        const size_t boff = (size_t)b * 128 * M_;
        pAh = g_Uhi + aoff; pAl = g_Ulo + aoff;
        pBh = g_sthi + boff; pBl = g_stlo + boff;
        po = outp + ((size_t)b * N_ + (size_t)rt * 128) * O_;
    }
    const __nv_bfloat16* mats[4] = {pAh, pAl, pBh, pBl};

    // ---- stage loader: 4 mats x 128 rows x 8 chunks(16B), XOR-8 swizzle ----
    auto load_stage = [&](int s, int kbase) {
        const uint32_t sd = sb + (uint32_t)(s & 1) * STAGEB;
#pragma unroll
        for (int mat = 0; mat < 4; mat++) {
            const __nv_bfloat16* bp = mats[mat];
#pragma unroll
            for (int j = 0; j < 4; j++) {
                const int rem = j * 256 + tid;       // 0..1023
                const int row = rem >> 3, ch = rem & 7;
                const uint32_t dst = sd + mat * MATB + row * 128 + ((ch ^ (row & 7)) << 4);
                cp16(dst, bp + (size_t)row * LD + kbase + ch * 8);
            }
        }
        cp_commit();
    };

    // warp tiling: 2(m) x 4(n); warp tile 64(m) x 32(n)
    const int wm = wid >> 2, wn = wid & 3;
    const int lane15 = lane & 15, hk = lane >> 4;   // hk selects k-half chunk
    const uint32_t rowA = wm * 64 + lane15;
    const uint32_t rowB = wn * 32 + lane15;
    const uint32_t offA = rowA * 128, xorA = rowA & 7;
    const uint32_t offB = rowB * 128, xorB = rowB & 7;

    float acc[4][4][4];
#pragma unroll
    for (int i = 0; i < 4; i++)
#pragma unroll
        for (int j = 0; j < 4; j++)
#pragma unroll
            for (int r = 0; r < 4; r++) acc[i][j][r] = 0.f;

    load_stage(0, 0);
    if (NS > 1) load_stage(1, KC);

    for (int s = 0; s < NS; s++) {
        if (s + 1 < NS) asm volatile("cp.async.wait_group 1;" ::: "memory");
        else            asm volatile("cp.async.wait_group 0;" ::: "memory");
        __syncthreads();

        const uint32_t sd  = sb + (uint32_t)(s & 1) * STAGEB;
        const uint32_t sAh = sd,           sAl = sd + MATB;
        const uint32_t sBh = sd + 2 * MATB, sBl = sd + 3 * MATB;

#pragma unroll
        for (int kk = 0; kk < 4; kk++) {   // 4 k16 steps per stage
            const uint32_t chA = (uint32_t)((2 * kk + hk) ^ xorA) << 4;
            const uint32_t chB = (uint32_t)((2 * kk + hk) ^ xorB) << 4;
            uint32_t ah[4][4], al[4][4], bh[4][2], bl[4][2];
#pragma unroll
            for (int mi = 0; mi < 4; mi++) {
                ldsm4(ah[mi][0], ah[mi][1], ah[mi][2], ah[mi][3],
                      sAh + offA + mi * 2048 + chA);
                ldsm4(al[mi][0], al[mi][1], al[mi][2], al[mi][3],
                      sAl + offA + mi * 2048 + chA);
            }
#pragma unroll
            for (int nb = 0; nb < 2; nb++) {
                uint32_t r0, r1, r2, r3;
                ldsm4(r0, r1, r2, r3, sBh + offB + nb * 2048 + chB);
                bh[nb * 2 + 0][0] = r0; bh[nb * 2 + 0][1] = r2;
                bh[nb * 2 + 1][0] = r1; bh[nb * 2 + 1][1] = r3;
                ldsm4(r0, r1, r2, r3, sBl + offB + nb * 2048 + chB);
                bl[nb * 2 + 0][0] = r0; bl[nb * 2 + 0][1] = r2;
                bl[nb * 2 + 1][0] = r1; bl[nb * 2 + 1][1] = r3;
            }
#pragma unroll
            for (int mi = 0; mi < 4; mi++)
#pragma unroll
                for (int ni = 0; ni < 4; ni++) {
                    mma_bf16(acc[mi][ni], ah[mi], bh[ni]);   // hi*hi
                    mma_bf16(acc[mi][ni], ah[mi], bl[ni]);   // hi*lo
                    mma_bf16(acc[mi][ni], al[mi], bh[ni]);   // lo*hi
                }
        }
        __syncthreads();
        if (s + 2 < NS) load_stage(s + 2, (s + 2) * KC);
    }

    // epilogue: write fp32 accumulators (ldo == 128 for all outputs)
    const int er = (lane >> 2), ec = (lane & 3) * 2;
#pragma unroll
    for (int mi = 0; mi < 4; mi++) {
        const int r0 = wm * 64 + mi * 16 + er;
#pragma unroll
        for (int ni = 0; ni < 4; ni++) {
            const int c = wn * 32 + ni * 8 + ec;
            *(float2*)(po + (size_t)r0 * 128 + c)       = make_float2(acc[mi][ni][0], acc[mi][ni][1]);
            *(float2*)(po + (size_t)(r0 + 8) * 128 + c) = make_float2(acc[mi][ni][2], acc[mi][ni][3]);
        }
    }
}

// ---------------- launch ---------------------------------------------------
extern "C" void kernel_launch(void* const* d_in, const int* in_sizes, int n_in,
                              void* d_out, int out_size) {
    const float* x = (const float*)d_in[0];   // [B, N, C]
    const float* U = (const float*)d_in[1];   // [N, M]
    const float* W = (const float*)d_in[2];   // [C, O, M]
    float* out = (float*)d_out;               // [B, N, O]

    cudaFuncSetAttribute(gemm_hmma<0>, cudaFuncAttributeMaxDynamicSharedMemorySize, GEMM_SMEM);
    cudaFuncSetAttribute(gemm_hmma<1>, cudaFuncAttributeMaxDynamicSharedMemorySize, GEMM_SMEM);

    // prep: splits + transposes
    p1_splitU<<<dim3(M_ / 32, N_ / 32), dim3(32, 8)>>>(U);
    p2_splitx<<<dim3(C_ / 32, N_ / 32, B_), dim3(32, 8)>>>(x);
    k2a_transpose<<<dim3(C_ * O_ / 32, M_ / 32), dim3(32, 8)>>>(W);

    // K1: x_spec = U^T x  (HMMA, split-K=2)
    gemm_hmma<0><<<dim3(M_ / 128, 2, B_), 256, GEMM_SMEM>>>(nullptr);
    reduce2<<<(B_ * M_ * C_) / 4 / 256, 256>>>();

    // K2: per-mode channel mixing (fp32)
    k2_mix<<<M_, 256>>>();

    // split S for K3
    p3_splitS<<<dim3(O_ / 32, M_ / 32, B_), dim3(32, 8)>>>();

    // K3: out = U S  (HMMA)
    gemm_hmma<1><<<dim3(N_ / 128, 1, B_), 256, GEMM_SMEM>>>(out);
}

// round 4
// speedup vs baseline: 3.8957x; 1.1128x over previous
#include <cuda_runtime.h>
#include <cuda_bf16.h>
#include <cstdint>

#define B_   32
#define N_   4096
#define C_   128
#define O_   128
#define M_   256

// ---------------- scratch (device globals; no allocation allowed) ----------
__device__ __align__(16) float g_outspec[B_ * M_ * O_];   // [b][m][o]
__device__ __align__(16) float g_wt[M_ * C_ * O_];        // [m][c][o]
__device__ __align__(16) float g_part[2 * B_ * M_ * C_];  // split-K partials (8 MB)

__device__ __align__(128) __nv_bfloat16 g_Uhi[N_ * M_];   // [n][m]  (A for K3)
__device__ __align__(128) __nv_bfloat16 g_Ulo[N_ * M_];
__device__ __align__(128) __nv_bfloat16 g_Uthi[M_ * N_];  // [m][n]  (A for K1)
__device__ __align__(128) __nv_bfloat16 g_Utlo[M_ * N_];
__device__ __align__(128) __nv_bfloat16 g_xthi[(size_t)B_ * C_ * N_]; // [b][c][n] (B for K1)
__device__ __align__(128) __nv_bfloat16 g_xtlo[(size_t)B_ * C_ * N_];
__device__ __align__(128) __nv_bfloat16 g_sthi[B_ * O_ * M_];         // [b][o][m] (B for K3)
__device__ __align__(128) __nv_bfloat16 g_stlo[B_ * O_ * M_];

// ---------------- helpers ---------------------------------------------------
__device__ __forceinline__ uint32_t smem_u32(const void* p) {
    uint32_t a;
    asm("{ .reg .u64 t; cvta.to.shared.u64 t, %1; cvt.u32.u64 %0, t; }" : "=r"(a) : "l"(p));
    return a;
}
__device__ __forceinline__ void cp16(uint32_t dst, const void* src) {
    asm volatile("cp.async.cg.shared.global [%0], [%1], 16;" :: "r"(dst), "l"(src));
}
__device__ __forceinline__ void cp_commit() {
    asm volatile("cp.async.commit_group;" ::: "memory");
}
__device__ __forceinline__ void ldsm4(uint32_t& r0, uint32_t& r1, uint32_t& r2, uint32_t& r3,
                                      uint32_t addr) {
    asm volatile("ldmatrix.sync.aligned.m8n8.x4.shared.b16 {%0,%1,%2,%3}, [%4];"
                 : "=r"(r0), "=r"(r1), "=r"(r2), "=r"(r3) : "r"(addr));
}
__device__ __forceinline__ void mma_bf16(float* d, const uint32_t* a, const uint32_t* b) {
    asm volatile("mma.sync.aligned.m16n8k16.row.col.f32.bf16.bf16.f32 "
                 "{%0,%1,%2,%3}, {%4,%5,%6,%7}, {%8,%9}, {%0,%1,%2,%3};"
                 : "+f"(d[0]), "+f"(d[1]), "+f"(d[2]), "+f"(d[3])
                 : "r"(a[0]), "r"(a[1]), "r"(a[2]), "r"(a[3]), "r"(b[0]), "r"(b[1]));
}
__device__ __forceinline__ void split2(float v, __nv_bfloat16& h, __nv_bfloat16& l) {
    h = __float2bfloat16_rn(v);
    l = __float2bfloat16_rn(v - __bfloat162float(h));
}

// ---------------- prep kernels ---------------------------------------------
__global__ __launch_bounds__(256) void p1_splitU(const float* __restrict__ U) {
    __shared__ float t[32][33];
    const int m0 = blockIdx.x * 32, n0 = blockIdx.y * 32;
    const int tx = threadIdx.x, ty = threadIdx.y;
#pragma unroll
    for (int i = 0; i < 32; i += 8) {
        float v = U[(size_t)(n0 + ty + i) * M_ + m0 + tx];
        t[ty + i][tx] = v;
        __nv_bfloat16 h, l; split2(v, h, l);
        g_Uhi[(size_t)(n0 + ty + i) * M_ + m0 + tx] = h;
        g_Ulo[(size_t)(n0 + ty + i) * M_ + m0 + tx] = l;
    }
    __syncthreads();
#pragma unroll
    for (int i = 0; i < 32; i += 8) {
        float v = t[tx][ty + i];
        __nv_bfloat16 h, l; split2(v, h, l);
        g_Uthi[(size_t)(m0 + ty + i) * N_ + n0 + tx] = h;
        g_Utlo[(size_t)(m0 + ty + i) * N_ + n0 + tx] = l;
    }
}

__global__ __launch_bounds__(256) void p2_splitx(const float* __restrict__ x) {
    __shared__ float t[32][33];
    const int c0 = blockIdx.x * 32, n0 = blockIdx.y * 32, b = blockIdx.z;
    const int tx = threadIdx.x, ty = threadIdx.y;
#pragma unroll
    for (int i = 0; i < 32; i += 8)
        t[ty + i][tx] = x[((size_t)b * N_ + n0 + ty + i) * C_ + c0 + tx];
    __syncthreads();
#pragma unroll
    for (int i = 0; i < 32; i += 8) {
        float v = t[tx][ty + i];
        __nv_bfloat16 h, l; split2(v, h, l);
        g_xthi[((size_t)b * C_ + c0 + ty + i) * N_ + n0 + tx] = h;
        g_xtlo[((size_t)b * C_ + c0 + ty + i) * N_ + n0 + tx] = l;
    }
}

__global__ __launch_bounds__(256) void p3_splitS() {
    __shared__ float t[32][33];
    const int o0 = blockIdx.x * 32, m0 = blockIdx.y * 32, b = blockIdx.z;
    const int tx = threadIdx.x, ty = threadIdx.y;
#pragma unroll
    for (int i = 0; i < 32; i += 8)
        t[ty + i][tx] = g_outspec[((size_t)b * M_ + m0 + ty + i) * O_ + o0 + tx];
    __syncthreads();
#pragma unroll
    for (int i = 0; i < 32; i += 8) {
        float v = t[tx][ty + i];
        __nv_bfloat16 h, l; split2(v, h, l);
        g_sthi[((size_t)b * O_ + o0 + ty + i) * M_ + m0 + tx] = h;
        g_stlo[((size_t)b * O_ + o0 + ty + i) * M_ + m0 + tx] = l;
    }
}

__global__ __launch_bounds__(256) void k2a_transpose(const float* __restrict__ W) {
    __shared__ float t[32][33];
    const int co0 = blockIdx.x * 32, m0 = blockIdx.y * 32;
    const int tx = threadIdx.x, ty = threadIdx.y;
#pragma unroll
    for (int i = 0; i < 32; i += 8)
        t[ty + i][tx] = W[(size_t)(co0 + ty + i) * M_ + m0 + tx];
    __syncthreads();
#pragma unroll
    for (int i = 0; i < 32; i += 8)
        g_wt[(size_t)(m0 + ty + i) * (C_ * O_) + co0 + tx] = t[tx][ty + i];
}

// K2: out_spec[b,m,o] = sum_c x_spec[b,m,c] * Wt[m][c][o]
// x_spec is read as the SUM of the two split-K partials (reduce fused here).
__global__ __launch_bounds__(256) void k2_mix() {
    __shared__ float xs[B_][C_];
    const int m = blockIdx.x;
    const int tid = threadIdx.x;
    for (int i = tid; i < B_ * C_; i += 256) {
        int b = i >> 7, c = i & 127;
        const size_t idx = ((size_t)b * M_ + m) * C_ + c;
        xs[b][c] = g_part[idx] + g_part[(size_t)B_ * M_ * C_ + idx];
    }
    __syncthreads();
    const int o = tid & 127;
    const int bh = tid >> 7;
    const float* w = g_wt + (size_t)m * C_ * O_;
    float acc[16];
#pragma unroll
    for (int i = 0; i < 16; i++) acc[i] = 0.f;
#pragma unroll 4
    for (int c = 0; c < C_; c++) {
        float wv = w[c * O_ + o];
#pragma unroll
        for (int bb = 0; bb < 16; bb++)
            acc[bb] += xs[bb * 2 + bh][c] * wv;
    }
#pragma unroll
    for (int bb = 0; bb < 16; bb++)
        g_outspec[((size_t)(bb * 2 + bh) * M_ + m) * O_ + o] = acc[bb];
}

// ---------------- HMMA bf16-split GEMM (mma.sync, frag-pipelined) ----------
#define KC        64
#define MATB      16384
#define STAGEB    65536
#define GEMM_SMEM 131072

__device__ __forceinline__ void load_frags(
    uint32_t (&ah)[4][4], uint32_t (&al)[4][4],
    uint32_t (&bh)[4][2], uint32_t (&bl)[4][2],
    uint32_t sd, int kk,
    uint32_t offA, uint32_t xorA, uint32_t offB, uint32_t xorB, int hk) {
    const uint32_t chA = (uint32_t)(((2 * kk + hk) ^ xorA) << 4);
    const uint32_t chB = (uint32_t)(((2 * kk + hk) ^ xorB) << 4);
    const uint32_t sAh = sd, sAl = sd + MATB, sBh = sd + 2 * MATB, sBl = sd + 3 * MATB;
#pragma unroll
    for (int mi = 0; mi < 4; mi++) {
        ldsm4(ah[mi][0], ah[mi][1], ah[mi][2], ah[mi][3], sAh + offA + mi * 2048 + chA);
        ldsm4(al[mi][0], al[mi][1], al[mi][2], al[mi][3], sAl + offA + mi * 2048 + chA);
    }
#pragma unroll
    for (int nb = 0; nb < 2; nb++) {
        uint32_t r0, r1, r2, r3;
        ldsm4(r0, r1, r2, r3, sBh + offB + nb * 2048 + chB);
        bh[nb * 2 + 0][0] = r0; bh[nb * 2 + 0][1] = r2;
        bh[nb * 2 + 1][0] = r1; bh[nb * 2 + 1][1] = r3;
        ldsm4(r0, r1, r2, r3, sBl + offB + nb * 2048 + chB);
        bl[nb * 2 + 0][0] = r0; bl[nb * 2 + 0][1] = r2;
        bl[nb * 2 + 1][0] = r1; bl[nb * 2 + 1][1] = r3;
    }
}

template <int MODE>   // 0: K1 (split-K=2), 1: K3
__global__ __launch_bounds__(256, 1) void gemm_hmma(float* __restrict__ outp) {
    extern __shared__ char smem[];
    const uint32_t sb = smem_u32(smem);
    const int tid = threadIdx.x, wid = tid >> 5, lane = tid & 31;
    const int rt = blockIdx.x, ks = blockIdx.y, b = blockIdx.z;

    constexpr int LD   = (MODE == 0) ? N_ : M_;
    constexpr int KLEN = (MODE == 0) ? (N_ / 2) : M_;
    constexpr int NS   = KLEN / KC;

    const __nv_bfloat16 *pAh, *pAl, *pBh, *pBl;
    float* po;
    if (MODE == 0) {
        const size_t aoff = (size_t)rt * 128 * N_ + (size_t)ks * KLEN;
        const size_t boff = (size_t)b * 128 * N_ + (size_t)ks * KLEN;
        pAh = g_Uthi + aoff; pAl = g_Utlo + aoff;
        pBh = g_xthi + boff; pBl = g_xtlo + boff;
        po = g_part + (size_t)ks * (B_ * M_ * C_) + (size_t)(b * 2 + rt) * (128 * 128);
    } else {
        const size_t aoff = (size_t)rt * 128 * M_;
        const size_t boff = (size_t)b * 128 * M_;
        pAh = g_Uhi + aoff; pAl = g_Ulo + aoff;
        pBh = g_sthi + boff; pBl = g_stlo + boff;
        po = outp + ((size_t)b * N_ + (size_t)rt * 128) * O_;
    }
    const __nv_bfloat16* mats[4] = {pAh, pAl, pBh, pBl};

    auto load_stage = [&](int s, int kbase) {
        const uint32_t sd = sb + (uint32_t)(s & 1) * STAGEB;
#pragma unroll
        for (int mat = 0; mat < 4; mat++) {
            const __nv_bfloat16* bp = mats[mat];
#pragma unroll
            for (int j = 0; j < 4; j++) {
                const int rem = j * 256 + tid;
                const int row = rem >> 3, ch = rem & 7;
                const uint32_t dst = sd + mat * MATB + row * 128 + ((ch ^ (row & 7)) << 4);
                cp16(dst, bp + (size_t)row * LD + kbase + ch * 8);
            }
        }
        cp_commit();
    };

    const int wm = wid >> 2, wn = wid & 3;
    const int lane15 = lane & 15, hk = lane >> 4;
    const uint32_t rowA = wm * 64 + lane15;
    const uint32_t rowB = wn * 32 + lane15;
    const uint32_t offA = rowA * 128, xorA = rowA & 7;
    const uint32_t offB = rowB * 128, xorB = rowB & 7;

    float acc[4][4][4];
#pragma unroll
    for (int i = 0; i < 4; i++)
#pragma unroll
        for (int j = 0; j < 4; j++)
#pragma unroll
            for (int r = 0; r < 4; r++) acc[i][j][r] = 0.f;

    // double-buffered register fragments; frag for k-step kk lives in buffer kk&1
    uint32_t ahf[2][4][4], alf[2][4][4], bhf[2][4][2], blf[2][4][2];

    load_stage(0, 0);
    if (NS > 1) load_stage(1, KC);
    if (NS > 1) asm volatile("cp.async.wait_group 1;" ::: "memory");
    else        asm volatile("cp.async.wait_group 0;" ::: "memory");
    __syncthreads();
    load_frags(ahf[0], alf[0], bhf[0], blf[0], sb, 0, offA, xorA, offB, xorB, hk);

    for (int s = 0; s < NS; s++) {
        const uint32_t sd  = sb + (uint32_t)(s & 1) * STAGEB;
        const uint32_t sdn = sb + (uint32_t)((s + 1) & 1) * STAGEB;
#pragma unroll
        for (int kk = 0; kk < 4; kk++) {
            const int cur = kk & 1, nxt = cur ^ 1;
            if (kk < 3) {
                load_frags(ahf[nxt], alf[nxt], bhf[nxt], blf[nxt],
                           sd, kk + 1, offA, xorA, offB, xorB, hk);
            } else if (s + 1 < NS) {
                asm volatile("cp.async.wait_group 0;" ::: "memory");
                __syncthreads();
                load_frags(ahf[nxt], alf[nxt], bhf[nxt], blf[nxt],
                           sdn, 0, offA, xorA, offB, xorB, hk);
                if (s + 2 < NS) load_stage(s + 2, (s + 2) * KC);
            }
            // product-major: accumulator reuse distance = 16 mmas
#pragma unroll
            for (int mi = 0; mi < 4; mi++)
#pragma unroll
                for (int ni = 0; ni < 4; ni++)
                    mma_bf16(acc[mi][ni], ahf[cur][mi], bhf[cur][ni]);   // hi*hi
#pragma unroll
            for (int mi = 0; mi < 4; mi++)
#pragma unroll
                for (int ni = 0; ni < 4; ni++)
                    mma_bf16(acc[mi][ni], ahf[cur][mi], blf[cur][ni]);   // hi*lo
#pragma unroll
            for (int mi = 0; mi < 4; mi++)
#pragma unroll
                for (int ni = 0; ni < 4; ni++)
                    mma_bf16(acc[mi][ni], alf[cur][mi], bhf[cur][ni]);   // lo*hi
        }
    }

    const int er = (lane >> 2), ec = (lane & 3) * 2;
#pragma unroll
    for (int mi = 0; mi < 4; mi++) {
        const int r0 = wm * 64 + mi * 16 + er;
#pragma unroll
        for (int ni = 0; ni < 4; ni++) {
            const int c = wn * 32 + ni * 8 + ec;
            *(float2*)(po + (size_t)r0 * 128 + c)       = make_float2(acc[mi][ni][0], acc[mi][ni][1]);
            *(float2*)(po + (size_t)(r0 + 8) * 128 + c) = make_float2(acc[mi][ni][2], acc[mi][ni][3]);
        }
    }
}

// ---------------- launch ---------------------------------------------------
extern "C" void kernel_launch(void* const* d_in, const int* in_sizes, int n_in,
                              void* d_out, int out_size) {
    const float* x = (const float*)d_in[0];   // [B, N, C]
    const float* U = (const float*)d_in[1];   // [N, M]
    const float* W = (const float*)d_in[2];   // [C, O, M]
    float* out = (float*)d_out;               // [B, N, O]

    cudaFuncSetAttribute(gemm_hmma<0>, cudaFuncAttributeMaxDynamicSharedMemorySize, GEMM_SMEM);
    cudaFuncSetAttribute(gemm_hmma<1>, cudaFuncAttributeMaxDynamicSharedMemorySize, GEMM_SMEM);

    // prep: splits + transposes
    p1_splitU<<<dim3(M_ / 32, N_ / 32), dim3(32, 8)>>>(U);
    p2_splitx<<<dim3(C_ / 32, N_ / 32, B_), dim3(32, 8)>>>(x);
    k2a_transpose<<<dim3(C_ * O_ / 32, M_ / 32), dim3(32, 8)>>>(W);

    // K1: x_spec = U^T x  (HMMA, split-K=2; reduction fused into k2_mix)
    gemm_hmma<0><<<dim3(M_ / 128, 2, B_), 256, GEMM_SMEM>>>(nullptr);

    // K2: per-mode channel mixing (fp32)
    k2_mix<<<M_, 256>>>();

    // split S for K3
    p3_splitS<<<dim3(O_ / 32, M_ / 32, B_), dim3(32, 8)>>>();

    // K3: out = U S  (HMMA)
    gemm_hmma<1><<<dim3(N_ / 128, 1, B_), 256, GEMM_SMEM>>>(out);
}